// round 16
// baseline (speedup 1.0000x reference)
#include <cuda_runtime.h>

// ============================================================================
// GCN 2-layer: out = GCN(relu(GCN(x, W1, b1)), W2, b2)  with symmetric norm
// R15 post-mortem: LDS.128 GEMM was NEUTRAL -> GEMM (~33us) already at FMA2
// floor; agg (~115us) is the bottleneck and runs ~2x above its ~54us L2-BW
// floor => latency/MLP-limited (dynamic-trip-count inner loop, MLP~4).
// R16: pad CSR rows to multiples of 8 with (src=0, w=0) entries so the agg
// inner loop is fixed 8-edge fully-unrolled blocks -> 8 independent LDG.128
// in flight. Padding is numerically exact (w=0) and its gathers hit the
// L1-resident row 0.
// Pipeline (graph-capturable, allocation-free):
//   1. init+detect  : deg=1, cnt=0, cursor=0; probe edge_index dtype
//   2. deg_count    : deg[col] += ew, cnt[col]++
//   3. scan1/2/3    : rowptr = exclusive_scan(round8(cnt)); dis = rsqrt(deg)
//   4. fill         : CSR by target node: (src, norm) pairs
//   5. pad          : fill per-row slack with (0, 0.0f)
//   6. gemm<128>    : g_t1 = x @ W1      (f32x2 FMA)
//   7. agg<128,RELU>: g_h  = relu(gather-agg(g_t1) + b1)   [MLP-8 inner]
//   8. gemm<64>     : g_t2 = g_h @ W2
//   9. agg<64>      : out  = gather-agg(g_t2) + b2         [MLP-8 inner]
// ============================================================================

#define N_CAP 50000
#define E_CAP 800000
#define EP_CAP 1200000   // padded CSR capacity: E + 7*N max

__device__ int   g_is64;
__device__ float g_deg[N_CAP];
__device__ float g_dis[N_CAP];
__device__ int   g_cnt[N_CAP];
__device__ int   g_rowptr[N_CAP + 1];
__device__ int   g_cursor[N_CAP];
__device__ int   g_blocksum[64];
__device__ int   g_csr_src[EP_CAP];
__device__ float g_csr_w[EP_CAP];
__device__ __align__(16) float g_t1[(size_t)N_CAP * 128];
__device__ __align__(16) float g_h[(size_t)N_CAP * 128];
__device__ __align__(16) float g_t2[(size_t)N_CAP * 64];

// ---------------------------------------------------------------------------
// helpers
// ---------------------------------------------------------------------------
__device__ __forceinline__ unsigned long long pack2(float lo, float hi) {
    unsigned long long r;
    asm("mov.b64 %0, {%1,%2};" : "=l"(r) : "f"(lo), "f"(hi));
    return r;
}
__device__ __forceinline__ void unpack2(unsigned long long v, float& lo, float& hi) {
    asm("mov.b64 {%0,%1}, %2;" : "=f"(lo), "=f"(hi) : "l"(v));
}
__device__ __forceinline__ void fma_f32x2(unsigned long long& d,
                                          unsigned long long a,
                                          unsigned long long b) {
    asm("fma.rn.f32x2 %0, %1, %2, %0;" : "+l"(d) : "l"(a), "l"(b));
}

__device__ __forceinline__ int edge_at(const void* ei, size_t idx) {
    if (g_is64) return (int)((const long long*)ei)[idx];
    return ((const int*)ei)[idx];
}

// ---------------------------------------------------------------------------
// 1. init + dtype probe
// ---------------------------------------------------------------------------
__global__ void init_kernel(const void* ei, int n) {
    int i = blockIdx.x * blockDim.x + threadIdx.x;
    if (i == 0) {
        const long long* p = (const long long*)ei;
        int ok = 1;
        for (int k = 0; k < 16; ++k) {
            long long v = p[k];
            if (v < 0 || v >= n) { ok = 0; break; }
        }
        g_is64 = ok;
    }
    if (i < n) {
        g_deg[i] = 1.0f;   // self-loop weight
        g_cnt[i] = 0;
        g_cursor[i] = 0;
    }
}

// ---------------------------------------------------------------------------
// 2. degree + count histogram (bounds-guarded)
// ---------------------------------------------------------------------------
__global__ void deg_count_kernel(const void* __restrict__ ei,
                                 const float* __restrict__ ew, int e, int n) {
    int i = blockIdx.x * blockDim.x + threadIdx.x;
    if (i < e) {
        int c = edge_at(ei, (size_t)e + i);
        if ((unsigned)c < (unsigned)n) {
            atomicAdd(&g_deg[c], ew[i]);
            atomicAdd(&g_cnt[c], 1);
        }
    }
}

// ---------------------------------------------------------------------------
// 3. scan (3-phase) over PADDED counts + dis = rsqrt(deg)
// ---------------------------------------------------------------------------
__global__ void scan1_kernel(int n) {
    __shared__ int wsum[32];
    int i = blockIdx.x * 1024 + threadIdx.x;
    int lane = threadIdx.x & 31, wid = threadIdx.x >> 5;
    int v = (i < n) ? ((g_cnt[i] + 7) & ~7) : 0;   // round up to multiple of 8
    int s = v;
#pragma unroll
    for (int d = 1; d < 32; d <<= 1) {
        int t = __shfl_up_sync(0xffffffffu, s, d);
        if (lane >= d) s += t;
    }
    if (lane == 31) wsum[wid] = s;
    __syncthreads();
    if (wid == 0) {
        int ws = wsum[lane];
#pragma unroll
        for (int d = 1; d < 32; d <<= 1) {
            int t = __shfl_up_sync(0xffffffffu, ws, d);
            if (lane >= d) ws += t;
        }
        wsum[lane] = ws;
    }
    __syncthreads();
    int off = (wid > 0) ? wsum[wid - 1] : 0;
    if (i < n) {
        g_rowptr[i] = off + s - v;              // block-local exclusive scan
        g_dis[i] = rsqrtf(g_deg[i]);            // deg >= 1 always (self loop)
    }
    if (threadIdx.x == 1023) g_blocksum[blockIdx.x] = off + s;
}

__global__ void scan2_kernel(int nb) {
    if (threadIdx.x == 0 && blockIdx.x == 0) {
        int run = 0;
        for (int b = 0; b < nb; ++b) {
            int t = g_blocksum[b];
            g_blocksum[b] = run;
            run += t;
        }
        g_blocksum[nb] = run;                   // grand total (padded edges)
    }
}

__global__ void scan3_kernel(int n, int nb) {
    int i = blockIdx.x * blockDim.x + threadIdx.x;
    if (i < n) g_rowptr[i] += g_blocksum[i >> 10];
    if (i == 0) g_rowptr[n] = g_blocksum[nb];
}

// ---------------------------------------------------------------------------
// 4. CSR fill with per-edge precomputed norm (bounds-guarded)
// ---------------------------------------------------------------------------
__global__ void fill_kernel(const void* __restrict__ ei,
                            const float* __restrict__ ew, int e, int n) {
    int i = blockIdx.x * blockDim.x + threadIdx.x;
    if (i < e) {
        int r = edge_at(ei, i);
        int c = edge_at(ei, (size_t)e + i);
        if ((unsigned)r < (unsigned)n && (unsigned)c < (unsigned)n) {
            float w = g_dis[r] * ew[i] * g_dis[c];
            int pos = g_rowptr[c] + atomicAdd(&g_cursor[c], 1);
            if ((unsigned)pos < (unsigned)EP_CAP) {
                g_csr_src[pos] = r;
                g_csr_w[pos] = w;
            }
        }
    }
}

// ---------------------------------------------------------------------------
// 5. pad each row's slack ([rowptr+cursor, rowptr+1)) with (0, 0.0f).
//    <=7 entries per node; w=0 makes them numerically exact no-ops.
// ---------------------------------------------------------------------------
__global__ void pad_kernel(int n) {
    int i = blockIdx.x * blockDim.x + threadIdx.x;
    if (i < n) {
        int p   = g_rowptr[i] + g_cursor[i];
        int end = g_rowptr[i + 1];
        for (; p < end; ++p) {
            g_csr_src[p] = 0;
            g_csr_w[p] = 0.0f;
        }
    }
}

// ---------------------------------------------------------------------------
// 6/8. GEMM: OUT[n][FOUT] = X[n][128] @ W[128][FOUT], f32x2 + LDS.128 feeds
// ---------------------------------------------------------------------------
template <int FOUT>
__global__ __launch_bounds__(256) void gemm_kernel(const float* __restrict__ Xext,
                                                   const float* __restrict__ W, int n) {
    const float* X;
    float* out;
    if constexpr (FOUT == 128) { X = Xext; out = g_t1; }
    else                       { X = g_h;  out = g_t2; }

    extern __shared__ unsigned long long smem[];
    ulonglong2* Wsm = (ulonglong2*)smem;                       // [32][FOUT]
    unsigned long long* Xsm = smem + 64 * FOUT;                // [64][66]

    const int tid = threadIdx.x;
    const int m0 = blockIdx.x * 64;

    for (int idx = tid; idx < 32 * FOUT; idx += 256) {
        int m = idx / FOUT, c = idx - m * FOUT;
        float a0 = W[(size_t)(4 * m + 0) * FOUT + c];
        float a1 = W[(size_t)(4 * m + 1) * FOUT + c];
        float a2 = W[(size_t)(4 * m + 2) * FOUT + c];
        float a3 = W[(size_t)(4 * m + 3) * FOUT + c];
        ulonglong2 v;
        v.x = pack2(a0, a1);
        v.y = pack2(a2, a3);
        Wsm[idx] = v;
    }
    for (int idx = tid; idx < 64 * 32; idx += 256) {
        int r = idx >> 5, q = idx & 31;
        float4 v = make_float4(0.f, 0.f, 0.f, 0.f);
        int row = m0 + r;
        if (row < n) v = *(const float4*)(X + (size_t)row * 128 + 4 * q);
        *((float4*)(Xsm + (size_t)r * 66) + q) = v;
    }
    __syncthreads();

    constexpr int CG  = FOUT / 4;
    constexpr int RG  = 256 / CG;
    constexpr int RPT = 64 / RG;

    const int tx = tid % CG;
    const int r0 = (tid / CG) * RPT;

    unsigned long long acc[RPT][4];
#pragma unroll
    for (int r = 0; r < RPT; ++r)
#pragma unroll
        for (int j = 0; j < 4; ++j) acc[r][j] = 0ull;

#pragma unroll 2
    for (int m = 0; m < 32; ++m) {
        ulonglong2 w[4];
#pragma unroll
        for (int j = 0; j < 4; ++j) w[j] = Wsm[m * FOUT + tx + CG * j];
#pragma unroll
        for (int r = 0; r < RPT; ++r) {
            ulonglong2 xp = *(const ulonglong2*)(Xsm + (size_t)(r0 + r) * 66 + 2 * m);
#pragma unroll
            for (int j = 0; j < 4; ++j) {
                fma_f32x2(acc[r][j], xp.x, w[j].x);
                fma_f32x2(acc[r][j], xp.y, w[j].y);
            }
        }
    }

#pragma unroll
    for (int r = 0; r < RPT; ++r) {
        int row = m0 + r0 + r;
        if (row < n) {
#pragma unroll
            for (int j = 0; j < 4; ++j) {
                float lo, hi;
                unpack2(acc[r][j], lo, hi);
                out[(size_t)row * FOUT + tx + CG * j] = lo + hi;
            }
        }
    }
}

// ---------------------------------------------------------------------------
// 7/9. Aggregation: warp-per-node CSR gather, MLP-8 inner loop over padded
//      rows (row length always a multiple of 8 -> fixed-trip unrolled blocks
//      with 8 independent gathers in flight).
// ---------------------------------------------------------------------------
template <int F, bool RELU>
__global__ __launch_bounds__(256) void agg_kernel(const float* __restrict__ bias,
                                                  float* __restrict__ outext, int n) {
    const float* t;
    float* out;
    if constexpr (F == 128) { t = g_t1; out = g_h; }
    else                    { t = g_t2; out = outext; }

    int node = (blockIdx.x * blockDim.x + threadIdx.x) >> 5;
    int lane = threadIdx.x & 31;
    if (node >= n) return;

    constexpr int V = F / 32;           // 4 (F=128) or 2 (F=64)
    float acc[V];
    float dn = g_dis[node];
    float ws = dn * dn;                  // self-loop norm (weight 1)

    const float* selfp = t + (size_t)node * F + V * lane;
    if constexpr (V == 4) {
        float4 v = *(const float4*)selfp;
        acc[0] = ws * v.x; acc[1] = ws * v.y; acc[2] = ws * v.z; acc[3] = ws * v.w;
    } else {
        float2 v = *(const float2*)selfp;
        acc[0] = ws * v.x; acc[1] = ws * v.y;
    }

    int beg = g_rowptr[node], end = g_rowptr[node + 1];   // length % 8 == 0
    for (int base = beg; base < end; base += 32) {
        int avail = min(32, end - base);                   // multiple of 8
        int src = 0; float w = 0.f;
        if (lane < avail) { src = g_csr_src[base + lane]; w = g_csr_w[base + lane]; }
        for (int jb = 0; jb < avail; jb += 8) {
#pragma unroll
            for (int j = 0; j < 8; ++j) {
                int   s  = __shfl_sync(0xffffffffu, src, jb + j);
                float wj = __shfl_sync(0xffffffffu, w,   jb + j);
                const float* p = t + (size_t)s * F + V * lane;
                if constexpr (V == 4) {
                    float4 v = *(const float4*)p;
                    acc[0] += wj * v.x; acc[1] += wj * v.y;
                    acc[2] += wj * v.z; acc[3] += wj * v.w;
                } else {
                    float2 v = *(const float2*)p;
                    acc[0] += wj * v.x; acc[1] += wj * v.y;
                }
            }
        }
    }

#pragma unroll
    for (int q = 0; q < V; ++q) {
        float r = acc[q] + bias[V * lane + q];
        if (RELU) r = fmaxf(r, 0.f);
        acc[q] = r;
    }
    float* o = out + (size_t)node * F + V * lane;
    if constexpr (V == 4) *(float4*)o = make_float4(acc[0], acc[1], acc[2], acc[3]);
    else                  *(float2*)o = make_float2(acc[0], acc[1]);
}

// ---------------------------------------------------------------------------
// launch
// ---------------------------------------------------------------------------
extern "C" void kernel_launch(void* const* d_in, const int* in_sizes, int n_in,
                              void* d_out, int out_size) {
    const float* x  = (const float*)d_in[0];
    const void*  ei = d_in[1];                  // int32 or int64 — probed on device
    const float* ew = (const float*)d_in[2];
    const float* W1 = (const float*)d_in[3];
    const float* b1 = (const float*)d_in[4];
    const float* W2 = (const float*)d_in[5];
    const float* b2 = (const float*)d_in[6];
    float* out = (float*)d_out;

    int n = in_sizes[0] / 128;   // 50000
    int e = in_sizes[2];         // 800000

    const int SMEM128 = (64 * 128 + 64 * 66) * 8;   // 99328 B
    const int SMEM64  = (64 * 64  + 64 * 66) * 8;   // 66560 B
    cudaFuncSetAttribute(gemm_kernel<128>, cudaFuncAttributeMaxDynamicSharedMemorySize, SMEM128);
    cudaFuncSetAttribute(gemm_kernel<64>,  cudaFuncAttributeMaxDynamicSharedMemorySize, SMEM64);

    int nb_scan = (n + 1023) / 1024;

    init_kernel<<<(n + 255) / 256, 256>>>(ei, n);
    deg_count_kernel<<<(e + 255) / 256, 256>>>(ei, ew, e, n);
    scan1_kernel<<<nb_scan, 1024>>>(n);
    scan2_kernel<<<1, 32>>>(nb_scan);
    scan3_kernel<<<(n + 255) / 256, 256>>>(n, nb_scan);
    fill_kernel<<<(e + 255) / 256, 256>>>(ei, ew, e, n);
    pad_kernel<<<(n + 255) / 256, 256>>>(n);

    // Layer 1: g_t1 = x @ W1 ; g_h = relu(agg(g_t1) + b1)
    gemm_kernel<128><<<(n + 63) / 64, 256, SMEM128>>>(x, W1, n);
    agg_kernel<128, true><<<(n * 32 + 255) / 256, 256>>>(b1, out, n);

    // Layer 2: g_t2 = g_h @ W2 ; out = agg(g_t2) + b2
    gemm_kernel<64><<<(n + 63) / 64, 256, SMEM64>>>(x, W2, n);
    agg_kernel<64, false><<<(n * 32 + 255) / 256, 256>>>(b2, out, n);
}

// round 17
// speedup vs baseline: 1.0506x; 1.0506x over previous
#include <cuda_runtime.h>

// ============================================================================
// GCN 2-layer: out = GCN(relu(GCN(x, W1, b1)), W2, b2)  with symmetric norm
// R16 post-mortem: CSR padding REGRESSED (+10us: +22% agg iterations; the
// dynamic-trip agg loop was already load-hoisted by ptxas -> not MLP-bound).
// R17: (1) revert padding; (2) fuse the 3-kernel scan chain (measured: scan1
// 5.3us + scan2 5.8us of pure serial latency + launch gaps) into ONE
// decoupled-lookback kernel (49 co-resident blocks, single-word publish).
// Launches: 11 -> 8.
// Pipeline (graph-capturable, allocation-free):
//   1. init+detect  : deg=1, cnt=0, cursor=0, pub=0; probe edge_index dtype
//   2. deg_count    : deg[col] += ew, cnt[col]++
//   3. scan_fused   : rowptr = exclusive_scan(cnt) via decoupled lookback;
//                     dis = rsqrt(deg); rowptr[n] = total
//   4. fill         : CSR by target node: (src, norm) pairs
//   5. gemm<128>    : g_t1 = x @ W1      (f32x2 FMA)
//   6. agg<128,RELU>: g_h  = relu(gather-agg(g_t1) + b1)
//   7. gemm<64>     : g_t2 = g_h @ W2
//   8. agg<64>      : out  = gather-agg(g_t2) + b2
// ============================================================================

#define N_CAP 50000
#define E_CAP 800000

__device__ int   g_is64;
__device__ float g_deg[N_CAP];
__device__ float g_dis[N_CAP];
__device__ int   g_cnt[N_CAP];
__device__ int   g_rowptr[N_CAP + 1];
__device__ int   g_cursor[N_CAP];
__device__ unsigned long long g_scan_pub[64];   // (1<<32)|aggregate per block
__device__ int   g_csr_src[E_CAP];
__device__ float g_csr_w[E_CAP];
__device__ __align__(16) float g_t1[(size_t)N_CAP * 128];
__device__ __align__(16) float g_h[(size_t)N_CAP * 128];
__device__ __align__(16) float g_t2[(size_t)N_CAP * 64];

// ---------------------------------------------------------------------------
// helpers
// ---------------------------------------------------------------------------
__device__ __forceinline__ unsigned long long pack2(float lo, float hi) {
    unsigned long long r;
    asm("mov.b64 %0, {%1,%2};" : "=l"(r) : "f"(lo), "f"(hi));
    return r;
}
__device__ __forceinline__ void unpack2(unsigned long long v, float& lo, float& hi) {
    asm("mov.b64 {%0,%1}, %2;" : "=f"(lo), "=f"(hi) : "l"(v));
}
__device__ __forceinline__ void fma_f32x2(unsigned long long& d,
                                          unsigned long long a,
                                          unsigned long long b) {
    asm("fma.rn.f32x2 %0, %1, %2, %0;" : "+l"(d) : "l"(a), "l"(b));
}

__device__ __forceinline__ int edge_at(const void* ei, size_t idx) {
    if (g_is64) return (int)((const long long*)ei)[idx];
    return ((const int*)ei)[idx];
}

// ---------------------------------------------------------------------------
// 1. init + dtype probe
// ---------------------------------------------------------------------------
__global__ void init_kernel(const void* ei, int n) {
    int i = blockIdx.x * blockDim.x + threadIdx.x;
    if (i == 0) {
        const long long* p = (const long long*)ei;
        int ok = 1;
        for (int k = 0; k < 16; ++k) {
            long long v = p[k];
            if (v < 0 || v >= n) { ok = 0; break; }
        }
        g_is64 = ok;
    }
    if (i < 64) g_scan_pub[i] = 0ull;
    if (i < n) {
        g_deg[i] = 1.0f;   // self-loop weight
        g_cnt[i] = 0;
        g_cursor[i] = 0;
    }
}

// ---------------------------------------------------------------------------
// 2. degree + count histogram (bounds-guarded)
// ---------------------------------------------------------------------------
__global__ void deg_count_kernel(const void* __restrict__ ei,
                                 const float* __restrict__ ew, int e, int n) {
    int i = blockIdx.x * blockDim.x + threadIdx.x;
    if (i < e) {
        int c = edge_at(ei, (size_t)e + i);
        if ((unsigned)c < (unsigned)n) {
            atomicAdd(&g_deg[c], ew[i]);
            atomicAdd(&g_cnt[c], 1);
        }
    }
}

// ---------------------------------------------------------------------------
// 3. fused single-pass scan (decoupled lookback) + dis = rsqrt(deg)
//    49 blocks of 1024 — all co-resident on 148 SMs, so the spin on
//    predecessors' published aggregates cannot deadlock. Publication is a
//    single 64-bit word ((1<<32)|aggregate): no separate flag/fence needed.
// ---------------------------------------------------------------------------
__global__ __launch_bounds__(1024) void scan_kernel(int n) {
    __shared__ int wsum[32];
    __shared__ int s_prefix;
    int i = blockIdx.x * 1024 + threadIdx.x;
    int lane = threadIdx.x & 31, wid = threadIdx.x >> 5;

    int v = (i < n) ? g_cnt[i] : 0;
    int s = v;
#pragma unroll
    for (int d = 1; d < 32; d <<= 1) {
        int t = __shfl_up_sync(0xffffffffu, s, d);
        if (lane >= d) s += t;
    }
    if (lane == 31) wsum[wid] = s;
    __syncthreads();
    if (wid == 0) {
        int ws = wsum[lane];
#pragma unroll
        for (int d = 1; d < 32; d <<= 1) {
            int t = __shfl_up_sync(0xffffffffu, ws, d);
            if (lane >= d) ws += t;
        }
        wsum[lane] = ws;
    }
    __syncthreads();
    int off = (wid > 0) ? wsum[wid - 1] : 0;          // block-local excl base
    int block_total = wsum[31];

    // Publish this block's aggregate immediately.
    if (threadIdx.x == 0)
        atomicExch(&g_scan_pub[blockIdx.x], (1ull << 32) | (unsigned)block_total);

    // Lookback: threads t < blockIdx.x each spin-read predecessor t's word,
    // then 2-warp reduce into the exclusive prefix.
    if (wid == 0 || wid == 1) {
        int t = threadIdx.x;                           // 0..63 covers 49 blocks
        int val = 0;
        if (t < blockIdx.x) {
            unsigned long long w;
            do { w = atomicAdd(&g_scan_pub[t], 0ull); } while (w == 0ull);
            val = (int)(w & 0xffffffffull);
        }
#pragma unroll
        for (int d = 16; d > 0; d >>= 1) val += __shfl_down_sync(0xffffffffu, val, d);
        if (lane == 0) wsum[wid] = val;
    }
    __syncthreads();
    if (threadIdx.x == 0) s_prefix = wsum[0] + wsum[1];
    __syncthreads();

    int prefix = s_prefix;
    if (i < n) {
        g_rowptr[i] = prefix + off + s - v;            // global exclusive scan
        g_dis[i] = rsqrtf(g_deg[i]);                   // deg >= 1 (self loop)
        if (i == n - 1) g_rowptr[n] = prefix + off + s;
    }
}

// ---------------------------------------------------------------------------
// 4. CSR fill with per-edge precomputed norm (bounds-guarded)
// ---------------------------------------------------------------------------
__global__ void fill_kernel(const void* __restrict__ ei,
                            const float* __restrict__ ew, int e, int n) {
    int i = blockIdx.x * blockDim.x + threadIdx.x;
    if (i < e) {
        int r = edge_at(ei, i);
        int c = edge_at(ei, (size_t)e + i);
        if ((unsigned)r < (unsigned)n && (unsigned)c < (unsigned)n) {
            float w = g_dis[r] * ew[i] * g_dis[c];
            int pos = g_rowptr[c] + atomicAdd(&g_cursor[c], 1);
            if ((unsigned)pos < (unsigned)E_CAP) {
                g_csr_src[pos] = r;
                g_csr_w[pos] = w;
            }
        }
    }
}

// ---------------------------------------------------------------------------
// 5/7. GEMM: OUT[n][FOUT] = X[n][128] @ W[128][FOUT], f32x2 + LDS.128 feeds
// ---------------------------------------------------------------------------
template <int FOUT>
__global__ __launch_bounds__(256) void gemm_kernel(const float* __restrict__ Xext,
                                                   const float* __restrict__ W, int n) {
    const float* X;
    float* out;
    if constexpr (FOUT == 128) { X = Xext; out = g_t1; }
    else                       { X = g_h;  out = g_t2; }

    extern __shared__ unsigned long long smem[];
    ulonglong2* Wsm = (ulonglong2*)smem;                       // [32][FOUT]
    unsigned long long* Xsm = smem + 64 * FOUT;                // [64][66]

    const int tid = threadIdx.x;
    const int m0 = blockIdx.x * 64;

    for (int idx = tid; idx < 32 * FOUT; idx += 256) {
        int m = idx / FOUT, c = idx - m * FOUT;
        float a0 = W[(size_t)(4 * m + 0) * FOUT + c];
        float a1 = W[(size_t)(4 * m + 1) * FOUT + c];
        float a2 = W[(size_t)(4 * m + 2) * FOUT + c];
        float a3 = W[(size_t)(4 * m + 3) * FOUT + c];
        ulonglong2 v;
        v.x = pack2(a0, a1);
        v.y = pack2(a2, a3);
        Wsm[idx] = v;
    }
    for (int idx = tid; idx < 64 * 32; idx += 256) {
        int r = idx >> 5, q = idx & 31;
        float4 v = make_float4(0.f, 0.f, 0.f, 0.f);
        int row = m0 + r;
        if (row < n) v = *(const float4*)(X + (size_t)row * 128 + 4 * q);
        *((float4*)(Xsm + (size_t)r * 66) + q) = v;
    }
    __syncthreads();

    constexpr int CG  = FOUT / 4;
    constexpr int RG  = 256 / CG;
    constexpr int RPT = 64 / RG;

    const int tx = tid % CG;
    const int r0 = (tid / CG) * RPT;

    unsigned long long acc[RPT][4];
#pragma unroll
    for (int r = 0; r < RPT; ++r)
#pragma unroll
        for (int j = 0; j < 4; ++j) acc[r][j] = 0ull;

#pragma unroll 2
    for (int m = 0; m < 32; ++m) {
        ulonglong2 w[4];
#pragma unroll
        for (int j = 0; j < 4; ++j) w[j] = Wsm[m * FOUT + tx + CG * j];
#pragma unroll
        for (int r = 0; r < RPT; ++r) {
            ulonglong2 xp = *(const ulonglong2*)(Xsm + (size_t)(r0 + r) * 66 + 2 * m);
#pragma unroll
            for (int j = 0; j < 4; ++j) {
                fma_f32x2(acc[r][j], xp.x, w[j].x);
                fma_f32x2(acc[r][j], xp.y, w[j].y);
            }
        }
    }

#pragma unroll
    for (int r = 0; r < RPT; ++r) {
        int row = m0 + r0 + r;
        if (row < n) {
#pragma unroll
            for (int j = 0; j < 4; ++j) {
                float lo, hi;
                unpack2(acc[r][j], lo, hi);
                out[(size_t)row * FOUT + tx + CG * j] = lo + hi;
            }
        }
    }
}

// ---------------------------------------------------------------------------
// 6/8. Aggregation: warp-per-node CSR gather (no scatter atomics).
//   F=128: t = g_t1, out = g_h  (+relu)
//   F=64 : t = g_t2, out = external d_out
//   acc = dis[n]^2 * t[n] + sum_e norm_e * t[src_e]; +bias
// ---------------------------------------------------------------------------
template <int F, bool RELU>
__global__ __launch_bounds__(256) void agg_kernel(const float* __restrict__ bias,
                                                  float* __restrict__ outext, int n) {
    const float* t;
    float* out;
    if constexpr (F == 128) { t = g_t1; out = g_h; }
    else                    { t = g_t2; out = outext; }

    int node = (blockIdx.x * blockDim.x + threadIdx.x) >> 5;
    int lane = threadIdx.x & 31;
    if (node >= n) return;

    constexpr int V = F / 32;           // 4 (F=128) or 2 (F=64)
    float acc[V];
    float dn = g_dis[node];
    float ws = dn * dn;                  // self-loop norm (weight 1)

    const float* selfp = t + (size_t)node * F + V * lane;
    if constexpr (V == 4) {
        float4 v = *(const float4*)selfp;
        acc[0] = ws * v.x; acc[1] = ws * v.y; acc[2] = ws * v.z; acc[3] = ws * v.w;
    } else {
        float2 v = *(const float2*)selfp;
        acc[0] = ws * v.x; acc[1] = ws * v.y;
    }

    int beg = g_rowptr[node], end = g_rowptr[node + 1];
    for (int base = beg; base < end; base += 32) {
        int cnt = min(32, end - base);
        int src = 0; float w = 0.f;
        if (lane < cnt) { src = g_csr_src[base + lane]; w = g_csr_w[base + lane]; }
#pragma unroll 4
        for (int j = 0; j < cnt; ++j) {
            int s = __shfl_sync(0xffffffffu, src, j);
            float wj = __shfl_sync(0xffffffffu, w, j);
            const float* p = t + (size_t)s * F + V * lane;
            if constexpr (V == 4) {
                float4 v = *(const float4*)p;
                acc[0] += wj * v.x; acc[1] += wj * v.y;
                acc[2] += wj * v.z; acc[3] += wj * v.w;
            } else {
                float2 v = *(const float2*)p;
                acc[0] += wj * v.x; acc[1] += wj * v.y;
            }
        }
    }

#pragma unroll
    for (int q = 0; q < V; ++q) {
        float r = acc[q] + bias[V * lane + q];
        if (RELU) r = fmaxf(r, 0.f);
        acc[q] = r;
    }
    float* o = out + (size_t)node * F + V * lane;
    if constexpr (V == 4) *(float4*)o = make_float4(acc[0], acc[1], acc[2], acc[3]);
    else                  *(float2*)o = make_float2(acc[0], acc[1]);
}

// ---------------------------------------------------------------------------
// launch
// ---------------------------------------------------------------------------
extern "C" void kernel_launch(void* const* d_in, const int* in_sizes, int n_in,
                              void* d_out, int out_size) {
    const float* x  = (const float*)d_in[0];
    const void*  ei = d_in[1];                  // int32 or int64 — probed on device
    const float* ew = (const float*)d_in[2];
    const float* W1 = (const float*)d_in[3];
    const float* b1 = (const float*)d_in[4];
    const float* W2 = (const float*)d_in[5];
    const float* b2 = (const float*)d_in[6];
    float* out = (float*)d_out;

    int n = in_sizes[0] / 128;   // 50000
    int e = in_sizes[2];         // 800000

    const int SMEM128 = (64 * 128 + 64 * 66) * 8;   // 99328 B
    const int SMEM64  = (64 * 64  + 64 * 66) * 8;   // 66560 B
    cudaFuncSetAttribute(gemm_kernel<128>, cudaFuncAttributeMaxDynamicSharedMemorySize, SMEM128);
    cudaFuncSetAttribute(gemm_kernel<64>,  cudaFuncAttributeMaxDynamicSharedMemorySize, SMEM64);

    int nb_scan = (n + 1023) / 1024;   // 49 blocks — all co-resident (<=148 SMs)

    init_kernel<<<(n + 255) / 256, 256>>>(ei, n);
    deg_count_kernel<<<(e + 255) / 256, 256>>>(ei, ew, e, n);
    scan_kernel<<<nb_scan, 1024>>>(n);
    fill_kernel<<<(e + 255) / 256, 256>>>(ei, ew, e, n);

    // Layer 1: g_t1 = x @ W1 ; g_h = relu(agg(g_t1) + b1)
    gemm_kernel<128><<<(n + 63) / 64, 256, SMEM128>>>(x, W1, n);
    agg_kernel<128, true><<<(n * 32 + 255) / 256, 256>>>(b1, out, n);

    // Layer 2: g_t2 = g_h @ W2 ; out = agg(g_t2) + b2
    gemm_kernel<64><<<(n + 63) / 64, 256, SMEM64>>>(x, W2, n);
    agg_kernel<64, false><<<(n * 32 + 255) / 256, 256>>>(b2, out, n);
}